// round 16
// baseline (speedup 1.0000x reference)
#include <cuda_runtime.h>
#include <cuda_fp16.h>

// MultiScaleDeformableAttention, GB300 sm_103a.
// B=4, Q=21760, NH=8, DH=32, NL=4, NP=4, S=21760
// levels (square): 128,64,32,16 ; element starts: 0,16384,20480,21504
//
// Layout (g_vdup, 89MB): per (b,h,cell s) one 128B block of 32 interleaved
// corner pairs { v_s[ch], v_{s+1}[ch] } fp16. x==Wl-1 second slot is junk
// (never read: base cell xb<=Wl-2).
//
// Kernel 1 (convert): warp per (b,h,strip of 8 cells): 9 coalesced f32 slice
//   loads (read-once), 8x cvt f32x2->f16x2, 8 single-line stores.
// Kernel 2 (main): warp per (b,q,h). Lane=(row bit4, parity bit3, quad 0-2).
//   One LDG.128 per TWO samples. EXPLICIT 4-STAGE PIPELINE with a 48-reg
//   budget (__launch_bounds__(256,5)): prologue loads samples 0-7 (4 LDG in
//   flight), steady state consumes v[k] and immediately reloads it with
//   sample pair k+4 (WAR on fixed-lat HFMA2 is cheap) -> sustained MLP=4.
//   R15's version fit a 33-reg budget, so ptxas serialized to MLP~2.
//   fp16 accumulators split levels{0,1}/{2,3}; f32 corner sum; xor8/xor16
//   reduce; lanes 0-7 STG.128.

#define FULLMASK 0xffffffffu

constexpr int kQ = 21760;
constexpr int kS = 21760;

__device__ __align__(256) __half g_vdup[(size_t)4 * 8 * 21760 * 64]; // 89MB

// ---------------------------------------------------------------------------
__global__ __launch_bounds__(256)
void convert_kernel(const float* __restrict__ value)
{
    const int warp = (blockIdx.x * 256 + threadIdx.x) >> 5;   // [0, 87040)
    const int lane = threadIdx.x & 31;

    const int bh    = warp / 2720;            // b*8 + h
    const int strip = warp - bh * 2720;
    const int b     = bh >> 3;
    const int h     = bh & 7;
    const int s0    = strip * 8;

    float f[9];
#pragma unroll
    for (int r = 0; r < 9; ++r) {
        const int s = (s0 + r < kS) ? s0 + r : kS - 1;        // clamp last strip
        f[r] = __ldg(value + ((size_t)(b * kS + s) * 8 + h) * 32 + lane);
    }

    __half* dst = g_vdup + ((size_t)bh * kS + s0) * 64 + lane * 2;
#pragma unroll
    for (int k = 0; k < 8; ++k) {
        const __half2 hv = __floats2half2_rn(f[k], f[k + 1]); // (c0, c1)
        *reinterpret_cast<__half2*>(dst + (size_t)k * 64) = hv;
    }
}

// ---------------------------------------------------------------------------
__global__ __launch_bounds__(256, 5)    // 48-reg budget: room for MLP=4
void msda_kernel(const float* __restrict__ loc,
                 const float* __restrict__ attw,
                 float* __restrict__ out)
{
    const int warp = (blockIdx.x * 256 + threadIdx.x) >> 5;   // (b*Q+q)*8+h
    const int lane = threadIdx.x & 31;
    const int h  = warp & 7;
    const int bq = warp >> 3;
    const int b  = bq / kQ;

    // ---- precompute: lane j = sample j top row, lane j+16 = bottom row -----
    const int j = lane & 15;
    const float2 lc = __ldg(reinterpret_cast<const float2*>(loc) + (size_t)warp * 16 + j);
    const float  aw = __ldg(attw + (size_t)warp * 16 + j);

    const int   lvl = j >> 2;
    const int   Wl  = 128 >> lvl;
    const float Wf  = (float)Wl;

    const float x  = lc.x * Wf - 0.5f;
    const float y  = lc.y * Wf - 0.5f;
    const float xf = floorf(x);
    const float yf = floorf(y);
    const int   x0 = (int)xf;            // in [-1, Wl-1]
    const int   y0 = (int)yf;
    const float fx = x - xf;
    const float fy = y - yf;

    // Clamp base cell to [0, Wl-2]; remap weights so clamped-away corners get 0.
    float wx0 = 1.0f - fx, wx1 = fx;
    int   xb  = x0;
    if (x0 < 0)      { xb = 0;      wx0 = fx;   wx1 = 0.0f; }
    if (x0 > Wl - 2) { xb = Wl - 2; wx0 = 0.0f; wx1 = 1.0f - fx; }
    float wy0 = 1.0f - fy, wy1 = fy;
    int   yb  = y0;
    if (y0 < 0)      { yb = 0;      wy0 = fy;   wy1 = 0.0f; }
    if (y0 > Wl - 2) { yb = Wl - 2; wy0 = 0.0f; wy1 = 1.0f - fy; }

    const int   row = lane >> 4;                  // 0 = top, 1 = bottom
    const float wyr = row ? wy1 : wy0;
    const __half2 wh = __floats2half2_rn(wyr * aw * wx0, wyr * aw * wx1);
    const unsigned Wu = *reinterpret_cast<const unsigned*>(&wh);

    // Byte offset of this (sample,row)'s 128B block within the level.
    const int offv = ((yb + row) * Wl + xb) << 7;

    // ---- main-loop lane roles ----------------------------------------------
    const int laneterm = ((lane >> 3) & 1) + (lane & 16);   // shfl src term

    const char* plane = reinterpret_cast<const char*>(
        g_vdup + (size_t)(b * 8 + h) * kS * 64) + (lane & 7) * 16;

    const int LSb[4] = {0, 16384 * 128, 20480 * 128, 21504 * 128};

    // ---- all parameter shfls (independent, cheap) ---------------------------
    int      o[8];
    unsigned wu[8];
#pragma unroll
    for (int k = 0; k < 8; ++k) {
        const int src = 2 * k + laneterm;
        o[k]  = __shfl_sync(FULLMASK, offv, src);
        wu[k] = __shfl_sync(FULLMASK, Wu,   src);
    }

    __half2 accA[4], accB[4];
#pragma unroll
    for (int i = 0; i < 4; ++i) {
        accA[i] = __half2half2(__ushort_as_half(0));
        accB[i] = __half2half2(__ushort_as_half(0));
    }

    // ---- 4-stage rotating load pipeline (MLP = 4) ---------------------------
    // iter k covers sample pair k: levels map k>>1 (k<4) / 2+(k>>1) (k>=4).
    uint4 v[4];
#pragma unroll
    for (int k = 0; k < 4; ++k)      // prologue: samples 0..7 in flight
        v[k] = __ldg(reinterpret_cast<const uint4*>(plane + LSb[k >> 1] + o[k]));

#pragma unroll
    for (int k = 0; k < 4; ++k) {    // steady: consume k, reload with k+4
        const __half2 w2 = *reinterpret_cast<const __half2*>(&wu[k]);
        const uint4 vv = v[k];
        v[k] = __ldg(reinterpret_cast<const uint4*>(plane + LSb[2 + (k >> 1)] + o[4 + k]));
        accA[0] = __hfma2(w2, *reinterpret_cast<const __half2*>(&vv.x), accA[0]);
        accA[1] = __hfma2(w2, *reinterpret_cast<const __half2*>(&vv.y), accA[1]);
        accA[2] = __hfma2(w2, *reinterpret_cast<const __half2*>(&vv.z), accA[2]);
        accA[3] = __hfma2(w2, *reinterpret_cast<const __half2*>(&vv.w), accA[3]);
    }

#pragma unroll
    for (int k = 0; k < 4; ++k) {    // epilogue: drain samples 8..15
        const __half2 w2 = *reinterpret_cast<const __half2*>(&wu[4 + k]);
        accB[0] = __hfma2(w2, *reinterpret_cast<const __half2*>(&v[k].x), accB[0]);
        accB[1] = __hfma2(w2, *reinterpret_cast<const __half2*>(&v[k].y), accB[1]);
        accB[2] = __hfma2(w2, *reinterpret_cast<const __half2*>(&v[k].z), accB[2]);
        accB[3] = __hfma2(w2, *reinterpret_cast<const __half2*>(&v[k].w), accB[3]);
    }

    // ---- combine level sets, corner pairs; reduce parity(8) + row(16) -------
    float r[4];
#pragma unroll
    for (int i = 0; i < 4; ++i) {
        const float2 fA = __half22float2(accA[i]);
        const float2 fB = __half22float2(accB[i]);
        r[i] = (fA.x + fB.x) + (fA.y + fB.y);     // corner0 + corner1
    }

#pragma unroll
    for (int m = 8; m <= 16; m <<= 1) {
        r[0] += __shfl_xor_sync(FULLMASK, r[0], m);
        r[1] += __shfl_xor_sync(FULLMASK, r[1], m);
        r[2] += __shfl_xor_sync(FULLMASK, r[2], m);
        r[3] += __shfl_xor_sync(FULLMASK, r[3], m);
    }

    if (lane < 8) {
        float4 o4 = make_float4(r[0], r[1], r[2], r[3]);
        *reinterpret_cast<float4*>(out + (size_t)bq * 256 + h * 32 + lane * 4) = o4;
    }
}

extern "C" void kernel_launch(void* const* d_in, const int* in_sizes, int n_in,
                              void* d_out, int out_size)
{
    const float* value = (const float*)d_in[0];
    const float* loc   = (const float*)d_in[3];
    const float* attw  = (const float*)d_in[4];
    float* out = (float*)d_out;

    convert_kernel<<<10880, 256>>>(value);       // 87040 warps
    msda_kernel<<<87040, 256>>>(loc, attw, out); // 696320 warps
}

// round 17
// speedup vs baseline: 1.2456x; 1.2456x over previous
#include <cuda_runtime.h>
#include <cuda_fp16.h>

// MultiScaleDeformableAttention, GB300 sm_103a.
// B=4, Q=21760, NH=8, DH=32, NL=4, NP=4, S=21760
// levels (square): 128,64,32,16 ; element starts: 0,16384,20480,21504
//
// Layout (g_vdup, 89MB): per (b,h,cell s) one 128B block of 32 interleaved
// corner pairs { v_s[ch], v_{s+1}[ch] } fp16. x==Wl-1 second slot is junk
// (never read: base cell xb<=Wl-2).
//
// Kernel 1 (convert): warp per (b,h,strip of 8 cells): 9 coalesced f32 slice
//   loads (read-once), 8x cvt f32x2->f16x2, 8 single-line stores.
// Kernel 2 (main): warp per (b,q,h). Lane=(row bit4, parity bit3, quad 0-2).
//   One LDG.128 per TWO samples. OCCUPANCY-FIRST build: launch_bounds(256,8)
//   caps regs at 32 -> 64-warp theoretical occupancy (R16 showed occupancy,
//   not per-warp MLP, is the latency hider). Only the 8 offsets are hoisted
//   (load addresses ready early); the packed half2 weight is shfl'd in-loop
//   (fixed-lat, never the stall). fp16 accumulators split levels{0,1}/{2,3};
//   f32 corner sum; xor8/xor16 reduce; lanes 0-7 STG.128.

#define FULLMASK 0xffffffffu

constexpr int kQ = 21760;
constexpr int kS = 21760;

__device__ __align__(256) __half g_vdup[(size_t)4 * 8 * 21760 * 64]; // 89MB

// ---------------------------------------------------------------------------
__global__ __launch_bounds__(256)
void convert_kernel(const float* __restrict__ value)
{
    const int warp = (blockIdx.x * 256 + threadIdx.x) >> 5;   // [0, 87040)
    const int lane = threadIdx.x & 31;

    const int bh    = warp / 2720;            // b*8 + h
    const int strip = warp - bh * 2720;
    const int b     = bh >> 3;
    const int h     = bh & 7;
    const int s0    = strip * 8;

    float f[9];
#pragma unroll
    for (int r = 0; r < 9; ++r) {
        const int s = (s0 + r < kS) ? s0 + r : kS - 1;        // clamp last strip
        f[r] = __ldg(value + ((size_t)(b * kS + s) * 8 + h) * 32 + lane);
    }

    __half* dst = g_vdup + ((size_t)bh * kS + s0) * 64 + lane * 2;
#pragma unroll
    for (int k = 0; k < 8; ++k) {
        const __half2 hv = __floats2half2_rn(f[k], f[k + 1]); // (c0, c1)
        *reinterpret_cast<__half2*>(dst + (size_t)k * 64) = hv;
    }
}

// ---------------------------------------------------------------------------
__global__ __launch_bounds__(256, 8)    // 32-reg cap: 64-warp occupancy
void msda_kernel(const float* __restrict__ loc,
                 const float* __restrict__ attw,
                 float* __restrict__ out)
{
    const int warp = (blockIdx.x * 256 + threadIdx.x) >> 5;   // (b*Q+q)*8+h
    const int lane = threadIdx.x & 31;
    const int h  = warp & 7;
    const int bq = warp >> 3;
    const int b  = bq / kQ;

    // ---- precompute: lane j = sample j top row, lane j+16 = bottom row -----
    const int j = lane & 15;
    const float2 lc = __ldg(reinterpret_cast<const float2*>(loc) + (size_t)warp * 16 + j);
    const float  aw = __ldg(attw + (size_t)warp * 16 + j);

    const int   lvl = j >> 2;
    const int   Wl  = 128 >> lvl;
    const float Wf  = (float)Wl;

    const float x  = lc.x * Wf - 0.5f;
    const float y  = lc.y * Wf - 0.5f;
    const float xf = floorf(x);
    const float yf = floorf(y);
    const int   x0 = (int)xf;            // in [-1, Wl-1]
    const int   y0 = (int)yf;
    const float fx = x - xf;
    const float fy = y - yf;

    // Clamp base cell to [0, Wl-2]; remap weights so clamped-away corners get 0.
    float wx0 = 1.0f - fx, wx1 = fx;
    int   xb  = x0;
    if (x0 < 0)      { xb = 0;      wx0 = fx;   wx1 = 0.0f; }
    if (x0 > Wl - 2) { xb = Wl - 2; wx0 = 0.0f; wx1 = 1.0f - fx; }
    float wy0 = 1.0f - fy, wy1 = fy;
    int   yb  = y0;
    if (y0 < 0)      { yb = 0;      wy0 = fy;   wy1 = 0.0f; }
    if (y0 > Wl - 2) { yb = Wl - 2; wy0 = 0.0f; wy1 = 1.0f - fy; }

    const int   row = lane >> 4;                  // 0 = top, 1 = bottom
    const float wyr = row ? wy1 : wy0;
    const __half2 wh = __floats2half2_rn(wyr * aw * wx0, wyr * aw * wx1);
    const unsigned Wu = *reinterpret_cast<const unsigned*>(&wh);

    // Byte offset of this (sample,row)'s 128B block within the level.
    const int offv = ((yb + row) * Wl + xb) << 7;

    // ---- main-loop lane roles ----------------------------------------------
    const int laneterm = ((lane >> 3) & 1) + (lane & 16);   // shfl src term

    const char* plane = reinterpret_cast<const char*>(
        g_vdup + (size_t)(b * 8 + h) * kS * 64) + (lane & 7) * 16;

    const int LSb[4] = {0, 16384 * 128, 20480 * 128, 21504 * 128};

    // ---- hoist the 8 offsets (addresses ready before any load) -------------
    int o[8];
#pragma unroll
    for (int k = 0; k < 8; ++k)
        o[k] = __shfl_sync(FULLMASK, offv, 2 * k + laneterm);

    __half2 accA[4], accB[4];
#pragma unroll
    for (int i = 0; i < 4; ++i) {
        accA[i] = __half2half2(__ushort_as_half(0));
        accB[i] = __half2half2(__ushort_as_half(0));
    }

    // ---- batch 0: samples 0..7 (levels 0,1) ---------------------------------
    {
        uint4 v[4];
#pragma unroll
        for (int k = 0; k < 4; ++k)
            v[k] = __ldg(reinterpret_cast<const uint4*>(plane + LSb[k >> 1] + o[k]));
#pragma unroll
        for (int k = 0; k < 4; ++k) {
            const unsigned wk = __shfl_sync(FULLMASK, Wu, 2 * k + laneterm);
            const __half2  w2 = *reinterpret_cast<const __half2*>(&wk);
            accA[0] = __hfma2(w2, *reinterpret_cast<const __half2*>(&v[k].x), accA[0]);
            accA[1] = __hfma2(w2, *reinterpret_cast<const __half2*>(&v[k].y), accA[1]);
            accA[2] = __hfma2(w2, *reinterpret_cast<const __half2*>(&v[k].z), accA[2]);
            accA[3] = __hfma2(w2, *reinterpret_cast<const __half2*>(&v[k].w), accA[3]);
        }
    }

    // ---- batch 1: samples 8..15 (levels 2,3) --------------------------------
    {
        uint4 v[4];
#pragma unroll
        for (int k = 0; k < 4; ++k)
            v[k] = __ldg(reinterpret_cast<const uint4*>(plane + LSb[2 + (k >> 1)] + o[4 + k]));
#pragma unroll
        for (int k = 0; k < 4; ++k) {
            const unsigned wk = __shfl_sync(FULLMASK, Wu, 2 * (4 + k) + laneterm);
            const __half2  w2 = *reinterpret_cast<const __half2*>(&wk);
            accB[0] = __hfma2(w2, *reinterpret_cast<const __half2*>(&v[k].x), accB[0]);
            accB[1] = __hfma2(w2, *reinterpret_cast<const __half2*>(&v[k].y), accB[1]);
            accB[2] = __hfma2(w2, *reinterpret_cast<const __half2*>(&v[k].z), accB[2]);
            accB[3] = __hfma2(w2, *reinterpret_cast<const __half2*>(&v[k].w), accB[3]);
        }
    }

    // ---- combine level sets, corner pairs; reduce parity(8) + row(16) -------
    float r[4];
#pragma unroll
    for (int i = 0; i < 4; ++i) {
        const float2 fA = __half22float2(accA[i]);
        const float2 fB = __half22float2(accB[i]);
        r[i] = (fA.x + fB.x) + (fA.y + fB.y);     // corner0 + corner1
    }

#pragma unroll
    for (int m = 8; m <= 16; m <<= 1) {
        r[0] += __shfl_xor_sync(FULLMASK, r[0], m);
        r[1] += __shfl_xor_sync(FULLMASK, r[1], m);
        r[2] += __shfl_xor_sync(FULLMASK, r[2], m);
        r[3] += __shfl_xor_sync(FULLMASK, r[3], m);
    }

    if (lane < 8) {
        float4 o4 = make_float4(r[0], r[1], r[2], r[3]);
        *reinterpret_cast<float4*>(out + (size_t)bq * 256 + h * 32 + lane * 4) = o4;
    }
}

extern "C" void kernel_launch(void* const* d_in, const int* in_sizes, int n_in,
                              void* d_out, int out_size)
{
    const float* value = (const float*)d_in[0];
    const float* loc   = (const float*)d_in[3];
    const float* attw  = (const float*)d_in[4];
    float* out = (float*)d_out;

    convert_kernel<<<10880, 256>>>(value);       // 87040 warps
    msda_kernel<<<87040, 256>>>(loc, attw, out); // 696320 warps
}